// round 5
// baseline (speedup 1.0000x reference)
#include <cuda_runtime.h>
#include <cuda_fp16.h>
#include <math_constants.h>

#define DIM   64
#define NMAX  100000
#define SLOTS 128          // max in-degree headroom (Poisson mean 32; P(>96) ~ 1e-20)

// Scratch (__device__ globals: allocation-free rule)
__device__ float   g_ss[NMAX];                       // features @ a_src
__device__ float   g_sd[NMAX];                       // features @ a_dst
__device__ int     g_cnt[NMAX];                      // per-dst cursor / degree
__device__ __align__(16) __half2 g_fh[NMAX * 32];    // fp16 feature table (12.8 MB)
__device__ __align__(16) int2    g_bkt[NMAX * SLOTS];// {src, lrelu score} per edge

// K1: warp handles 2 nodes, 16 lanes per node. Coalesced row read, shuffle-
// reduced dots with both attn_w halves, fp16 feature table emit.
__global__ void k_prep(const float* __restrict__ feat,
                       const float* __restrict__ attn_w, int n)
{
    int w    = (blockIdx.x * blockDim.x + threadIdx.x) >> 5;
    int lane = threadIdx.x & 31;
    int node = w * 2 + (lane >> 4);
    int q    = lane & 15;
    if (node >= n) return;

    float4 v = __ldg((const float4*)(feat + (size_t)node * DIM) + q);
    float4 a = __ldg((const float4*)attn_w + q);
    float4 b = __ldg((const float4*)attn_w + 16 + q);
    float sa = v.x * a.x + v.y * a.y + v.z * a.z + v.w * a.w;
    float sb = v.x * b.x + v.y * b.y + v.z * b.z + v.w * b.w;
#pragma unroll
    for (int o = 8; o; o >>= 1) {
        sa += __shfl_xor_sync(~0u, sa, o);
        sb += __shfl_xor_sync(~0u, sb, o);
    }

    union { uint2 u; __half2 h[2]; } pk;
    pk.h[0] = __floats2half2_rn(v.x, v.y);
    pk.h[1] = __floats2half2_rn(v.z, v.w);
    *(uint2*)(g_fh + (size_t)node * 32 + 2 * q) = pk.u;

    if (q == 0) {
        g_ss[node]  = sa;
        g_sd[node]  = sb;
        g_cnt[node] = 0;
    }
}

// K2: bucket-scatter 4 edges per thread (int4 index loads, 4 indep chains).
__global__ void k_scatter(const int* __restrict__ src,
                          const int* __restrict__ dst, int e)
{
    int i4   = blockIdx.x * blockDim.x + threadIdx.x;
    int base = i4 * 4;
    if (base >= e) return;

    if (base + 4 <= e) {
        int4 s4 = __ldg((const int4*)src + i4);
        int4 d4 = __ldg((const int4*)dst + i4);
        int ss[4] = {s4.x, s4.y, s4.z, s4.w};
        int dd[4] = {d4.x, d4.y, d4.z, d4.w};
        float xs[4];
#pragma unroll
        for (int k = 0; k < 4; k++) {
            float t = g_ss[ss[k]] + g_sd[dd[k]];
            xs[k] = (t > 0.f) ? t : 0.01f * t;   // leaky_relu(0.01)
        }
#pragma unroll
        for (int k = 0; k < 4; k++) {
            int pos = atomicAdd(&g_cnt[dd[k]], 1);
            g_bkt[(size_t)dd[k] * SLOTS + pos] = make_int2(ss[k], __float_as_int(xs[k]));
        }
    } else {
        for (int i = base; i < e; i++) {
            int s = __ldg(src + i), d = __ldg(dst + i);
            float t = g_ss[s] + g_sd[d];
            t = (t > 0.f) ? t : 0.01f * t;
            int pos = atomicAdd(&g_cnt[d], 1);
            g_bkt[(size_t)d * SLOTS + pos] = make_int2(s, __float_as_int(t));
        }
    }
}

// K3: one warp per node, online softmax. The 32-edge chunk is processed as a
// fully-unrolled batch: all 8 shuffle-pairs + all 8 LDG.128s issued before any
// consumption -> MLP=8 per lane, L2 latency amortized 8x.
__global__ void __launch_bounds__(256) k_agg(float* __restrict__ out, int n)
{
    int warp = (blockIdx.x * blockDim.x + threadIdx.x) >> 5;
    int lane = threadIdx.x & 31;
    if (warp >= n) return;

    int cnt = g_cnt[warp];
    const int2* row = g_bkt + (size_t)warp * SLOTS;

    int grp = lane >> 3;     // edge sub-slot within a group of 4
    int q   = lane & 7;      // owns dims [8q, 8q+8)

    float mx = -CUDART_INF_F, dsum = 0.f;
    float acc[8] = {0.f, 0.f, 0.f, 0.f, 0.f, 0.f, 0.f, 0.f};

    for (int base = 0; base < cnt; base += 32) {
        int i = base + lane;
        int s = 0;
        float x = -CUDART_INF_F;
        if (i < cnt) {
            int2 p = __ldg(row + i);
            s = p.x;
            x = __int_as_float(p.y);
        }
        // chunk max -> rescale running accumulators (online softmax)
        float cm = x;
#pragma unroll
        for (int o = 16; o; o >>= 1) cm = fmaxf(cm, __shfl_xor_sync(~0u, cm, o));
        float nm = fmaxf(mx, cm);
        float sc = __expf(mx - nm);              // 0 on first chunk
        dsum *= sc;
#pragma unroll
        for (int k = 0; k < 8; k++) acc[k] *= sc;
        mx = nm;

        float ee = __expf(x - mx);               // 0 for lanes past cnt
        dsum += ee;

        // Batched gather phase: lanes past cnt hold ee=0/s=0, so tail
        // iterations contribute 0 and gather row 0 (L1-hit). No predication.
        float ew[8];
        uint4 u[8];
#pragma unroll
        for (int it = 0; it < 8; it++) {
            int   jj = it * 4 + grp;
            ew[it] = __shfl_sync(~0u, ee, jj);
            int   sw = __shfl_sync(~0u, s,  jj);
            u[it] = __ldg((const uint4*)(g_fh + (size_t)sw * 32) + q);
        }
#pragma unroll
        for (int it = 0; it < 8; it++) {
            const __half2* hp = (const __half2*)&u[it];
            float w = ew[it];
#pragma unroll
            for (int k = 0; k < 4; k++) {
                float2 f = __half22float2(hp[k]);
                acc[2 * k]     += w * f.x;
                acc[2 * k + 1] += w * f.y;
            }
        }
    }

#pragma unroll
    for (int o = 16; o; o >>= 1) dsum += __shfl_xor_sync(~0u, dsum, o);

    // fold the 4 edge sub-slots: lane L += L+16, then += L+8
#pragma unroll
    for (int k = 0; k < 8; k++) {
        acc[k] += __shfl_down_sync(~0u, acc[k], 16);
        acc[k] += __shfl_down_sync(~0u, acc[k], 8);
    }

    if (lane < 8) {
        float inv = (dsum > 0.f) ? __frcp_rn(dsum) : 0.f;
        float r[8];
#pragma unroll
        for (int k = 0; k < 8; k++) {
            float h = acc[k] * inv;
            r[k] = (h > 0.f) ? h : expm1f(h);
        }
        float4* o4 = (float4*)(out + (size_t)warp * DIM + q * 8);
        o4[0] = make_float4(r[0], r[1], r[2], r[3]);
        o4[1] = make_float4(r[4], r[5], r[6], r[7]);
    }
}

extern "C" void kernel_launch(void* const* d_in, const int* in_sizes, int n_in,
                              void* d_out, int out_size)
{
    const float* feat = (const float*)d_in[0];
    const float* attn = (const float*)d_in[1];
    const int*   src  = (const int*)d_in[2];
    const int*   dst  = (const int*)d_in[3];
    float* out = (float*)d_out;

    int n = in_sizes[0] / DIM;
    int e = in_sizes[2];

    long long pt = (long long)((n + 1) / 2) * 32;
    k_prep   <<<(unsigned)((pt + 255) / 256), 256>>>(feat, attn, n);
    k_scatter<<<((e + 3) / 4 + 255) / 256, 256>>>(src, dst, e);

    long long tt = (long long)n * 32;
    k_agg    <<<(unsigned)((tt + 255) / 256), 256>>>(out, n);
}

// round 7
// speedup vs baseline: 1.5572x; 1.5572x over previous
#include <cuda_runtime.h>
#include <cuda_fp16.h>
#include <math_constants.h>

#define DIM   64
#define NMAX  100000
#define SLOTS 128          // max in-degree headroom (Poisson mean 32; P(>96) ~ 1e-20)

// Scratch (__device__ globals: allocation-free rule)
__device__ float   g_ss[NMAX];                       // features @ a_src
__device__ float   g_sd[NMAX];                       // features @ a_dst
__device__ int     g_cnt[NMAX];                      // per-dst cursor / degree
__device__ __align__(16) __half2 g_fh[NMAX * 32];    // fp16 feature table (12.8 MB)
__device__ int     g_bs[NMAX * SLOTS];               // src-only buckets (4 B/edge)

// K1: warp handles 2 nodes, 16 lanes per node. Coalesced row read, shuffle-
// reduced dots with both attn_w halves, fp16 feature table emit.
__global__ void k_prep(const float* __restrict__ feat,
                       const float* __restrict__ attn_w, int n)
{
    int w    = (blockIdx.x * blockDim.x + threadIdx.x) >> 5;
    int lane = threadIdx.x & 31;
    int node = w * 2 + (lane >> 4);
    int q    = lane & 15;
    if (node >= n) return;

    float4 v = __ldg((const float4*)(feat + (size_t)node * DIM) + q);
    float4 a = __ldg((const float4*)attn_w + q);
    float4 b = __ldg((const float4*)attn_w + 16 + q);
    float sa = v.x * a.x + v.y * a.y + v.z * a.z + v.w * a.w;
    float sb = v.x * b.x + v.y * b.y + v.z * b.z + v.w * b.w;
#pragma unroll
    for (int o = 8; o; o >>= 1) {
        sa += __shfl_xor_sync(~0u, sa, o);
        sb += __shfl_xor_sync(~0u, sb, o);
    }

    union { uint2 u; __half2 h[2]; } pk;
    pk.h[0] = __floats2half2_rn(v.x, v.y);
    pk.h[1] = __floats2half2_rn(v.z, v.w);
    *(uint2*)(g_fh + (size_t)node * 32 + 2 * q) = pk.u;

    if (q == 0) {
        g_ss[node]  = sa;
        g_sd[node]  = sb;
        g_cnt[node] = 0;
    }
}

// K2: slim bucket-scatter: 4 edges/thread, no score math, no random gathers.
// Just atomic cursor + 4 B store of src.
__global__ void k_scatter(const int* __restrict__ src,
                          const int* __restrict__ dst, int e)
{
    int i4   = blockIdx.x * blockDim.x + threadIdx.x;
    int base = i4 * 4;
    if (base >= e) return;

    if (base + 4 <= e) {
        int4 s4 = __ldg((const int4*)src + i4);
        int4 d4 = __ldg((const int4*)dst + i4);
        int ss[4] = {s4.x, s4.y, s4.z, s4.w};
        int dd[4] = {d4.x, d4.y, d4.z, d4.w};
#pragma unroll
        for (int k = 0; k < 4; k++) {
            int pos = atomicAdd(&g_cnt[dd[k]], 1);
            g_bs[(size_t)dd[k] * SLOTS + pos] = ss[k];
        }
    } else {
        for (int i = base; i < e; i++) {
            int s = __ldg(src + i), d = __ldg(dst + i);
            int pos = atomicAdd(&g_cnt[d], 1);
            g_bs[(size_t)d * SLOTS + pos] = s;
        }
    }
}

// K3: one warp per node, online softmax. Scores recomputed here (g_sd is a
// per-node broadcast). Gather loop is depth-2 software-pipelined: next group's
// shuffles + LDG issued before consuming the current group (MLP_p1=2, avoids
// the R5 L1tex-queue-contention regime).
__global__ void k_agg(float* __restrict__ out, int n)
{
    int warp = (blockIdx.x * blockDim.x + threadIdx.x) >> 5;
    int lane = threadIdx.x & 31;
    if (warp >= n) return;

    int cnt = g_cnt[warp];
    const int* row = g_bs + (size_t)warp * SLOTS;
    float sd = g_sd[warp];

    int grp = lane >> 3;     // edge sub-slot within a group of 4
    int q   = lane & 7;      // owns dims [8q, 8q+8)

    float mx = -CUDART_INF_F, dsum = 0.f;
    float acc[8] = {0.f, 0.f, 0.f, 0.f, 0.f, 0.f, 0.f, 0.f};

    for (int base = 0; base < cnt; base += 32) {
        int i = base + lane;
        int s = 0;
        float x = -CUDART_INF_F;
        if (i < cnt) {
            s = __ldg(row + i);
            float t = g_ss[s] + sd;
            x = (t > 0.f) ? t : 0.01f * t;       // leaky_relu(0.01)
        }
        // chunk max -> rescale running accumulators (online softmax)
        float cm = x;
#pragma unroll
        for (int o = 16; o; o >>= 1) cm = fmaxf(cm, __shfl_xor_sync(~0u, cm, o));
        float nm = fmaxf(mx, cm);
        float sc = __expf(mx - nm);              // 0 on first chunk
        dsum *= sc;
#pragma unroll
        for (int k = 0; k < 8; k++) acc[k] *= sc;
        mx = nm;

        float ee = __expf(x - mx);               // 0 for lanes past cnt
        dsum += ee;

        int c = min(32, cnt - base);
        int iters = (c + 3) >> 2;                // 4-edge groups this chunk

        // pipelined gather: group g+1 in flight while consuming group g
        float ewc = __shfl_sync(~0u, ee, grp);
        int   swc = __shfl_sync(~0u, s,  grp);
        uint4 uc  = __ldg((const uint4*)(g_fh + (size_t)swc * 32) + q);
        for (int it = 1; it < iters; it++) {
            int   jj  = it * 4 + grp;            // zero-weight lanes on tail: harmless
            float ewn = __shfl_sync(~0u, ee, jj);
            int   swn = __shfl_sync(~0u, s,  jj);
            uint4 un  = __ldg((const uint4*)(g_fh + (size_t)swn * 32) + q);

            const __half2* hp = (const __half2*)&uc;
#pragma unroll
            for (int k = 0; k < 4; k++) {
                float2 f = __half22float2(hp[k]);
                acc[2 * k]     += ewc * f.x;
                acc[2 * k + 1] += ewc * f.y;
            }
            uc = un; ewc = ewn;
        }
        const __half2* hp = (const __half2*)&uc;
#pragma unroll
        for (int k = 0; k < 4; k++) {
            float2 f = __half22float2(hp[k]);
            acc[2 * k]     += ewc * f.x;
            acc[2 * k + 1] += ewc * f.y;
        }
    }

#pragma unroll
    for (int o = 16; o; o >>= 1) dsum += __shfl_xor_sync(~0u, dsum, o);

    // fold the 4 edge sub-slots: lane L += L+16, then += L+8
#pragma unroll
    for (int k = 0; k < 8; k++) {
        acc[k] += __shfl_down_sync(~0u, acc[k], 16);
        acc[k] += __shfl_down_sync(~0u, acc[k], 8);
    }

    if (lane < 8) {
        float inv = (dsum > 0.f) ? __frcp_rn(dsum) : 0.f;
        float r[8];
#pragma unroll
        for (int k = 0; k < 8; k++) {
            float h = acc[k] * inv;
            r[k] = (h > 0.f) ? h : expm1f(h);
        }
        float4* o4 = (float4*)(out + (size_t)warp * DIM + q * 8);
        o4[0] = make_float4(r[0], r[1], r[2], r[3]);
        o4[1] = make_float4(r[4], r[5], r[6], r[7]);
    }
}

extern "C" void kernel_launch(void* const* d_in, const int* in_sizes, int n_in,
                              void* d_out, int out_size)
{
    const float* feat = (const float*)d_in[0];
    const float* attn = (const float*)d_in[1];
    const int*   src  = (const int*)d_in[2];
    const int*   dst  = (const int*)d_in[3];
    float* out = (float*)d_out;

    int n = in_sizes[0] / DIM;
    int e = in_sizes[2];

    long long pt = (long long)((n + 1) / 2) * 32;
    k_prep   <<<(unsigned)((pt + 255) / 256), 256>>>(feat, attn, n);
    k_scatter<<<((e + 3) / 4 + 255) / 256, 256>>>(src, dst, e);

    long long tt = (long long)n * 32;
    k_agg    <<<(unsigned)((tt + 255) / 256), 256>>>(out, n);
}